// round 6
// baseline (speedup 1.0000x reference)
#include <cuda_runtime.h>
#include <cstdint>
#include <cstddef>

#define NAGENTS 32768
#define HDIM    256
#define NGROUP  1024
#define NSTEPS  (NAGENTS + 1)

// ---------------- scratch (__device__ globals; no allocation) ----------------
__device__ float g_goal[HDIM];
__device__ float g_pooled[NGROUP * HDIM];
__device__ float g_Z[(NGROUP + 1) * 4 * HDIM];
__device__ int   g_rowgroup[NAGENTS];
__device__ float g_hs[(size_t)NSTEPS * HDIM];

// ---------------- helpers ----------------
__device__ __forceinline__ unsigned smem_u32(const void* p) {
    return (unsigned)__cvta_generic_to_shared(p);
}
__device__ __forceinline__ unsigned cluster_rank_() {
    unsigned r; asm("mov.u32 %0, %%cluster_ctarank;" : "=r"(r)); return r;
}
__device__ __forceinline__ void cluster_sync_() {
    asm volatile("barrier.cluster.arrive.aligned;\n\tbarrier.cluster.wait.aligned;" ::: "memory");
}
// fast nonlinearities: single-MUFU tanh
__device__ __forceinline__ float tanh_a(float x) {
    float y; asm("tanh.approx.f32 %0, %1;" : "=f"(y) : "f"(x)); return y;
}
__device__ __forceinline__ float sigm_a(float x) {
    return fmaf(0.5f, tanh_a(0.5f * x), 0.5f);
}
// packed fp32x2 FFMA2 (PTX-only)
__device__ __forceinline__ void ffma2(unsigned long long& d, unsigned long long a, unsigned long long b) {
    asm("fma.rn.f32x2 %0, %1, %2, %0;" : "+l"(d) : "l"(a), "l"(b));
}
__device__ __forceinline__ unsigned long long pack2(float lo, float hi) {
    unsigned long long r; asm("mov.b64 %0, {%1, %2};" : "=l"(r) : "f"(lo), "f"(hi)); return r;
}
__device__ __forceinline__ float pairsum(unsigned long long v) {
    float lo, hi; asm("mov.b64 {%0, %1}, %2;" : "=f"(lo), "=f"(hi) : "l"(v));
    return lo + hi;
}
// mbarrier ops
__device__ __forceinline__ void mbar_init(unsigned a, unsigned cnt) {
    asm volatile("mbarrier.init.shared.b64 [%0], %1;" :: "r"(a), "r"(cnt) : "memory");
}
__device__ __forceinline__ void mbar_expect_tx(unsigned a, unsigned bytes) {
    asm volatile("mbarrier.arrive.expect_tx.shared.b64 _, [%0], %1;" :: "r"(a), "r"(bytes) : "memory");
}
__device__ __forceinline__ void mbar_wait_cluster(unsigned a, unsigned parity) {
    asm volatile(
        "{\n\t"
        ".reg .pred P;\n\t"
        "WAIT_%=:\n\t"
        "mbarrier.try_wait.parity.acquire.cluster.shared::cta.b64 P, [%0], %1, 0x989680;\n\t"
        "@P bra.uni DONE_%=;\n\t"
        "bra.uni WAIT_%=;\n\t"
        "DONE_%=:\n\t"
        "}"
        :: "r"(a), "r"(parity) : "memory");
}
// DSMEM bulk copy: local SMEM -> peer CTA SMEM, complete_tx on peer's mbarrier
__device__ __forceinline__ void bulk_dsmem(unsigned dst, unsigned src, unsigned bytes, unsigned mbar) {
    asm volatile("cp.async.bulk.shared::cluster.shared::cta.mbarrier::complete_tx::bytes "
                 "[%0], [%1], %2, [%3];"
                 :: "r"(dst), "r"(src), "r"(bytes), "r"(mbar) : "memory");
}
__device__ __forceinline__ void fence_async_shared() {
    asm volatile("fence.proxy.async.shared::cta;" ::: "memory");
}

// ---------------- goal embedding ----------------
__global__ void __launch_bounds__(256) goal_kernel(const float* __restrict__ gs_in,
                                                   const float* __restrict__ Wg,
                                                   const float* __restrict__ bg) {
    __shared__ float gs[HDIM];
    int c = threadIdx.x;
    gs[c] = gs_in[c];
    __syncthreads();
    float acc = bg[c];
#pragma unroll 8
    for (int k = 0; k < HDIM; k++) acc = fmaf(gs[k], Wg[k * HDIM + c], acc);
    g_goal[c] = fmaxf(acc, 0.f);
}

// ---------------- inverse scatter map ----------------
__global__ void rowgroup_kernel(const int* __restrict__ groups) {
    int i = blockIdx.x * blockDim.x + threadIdx.x;
    g_rowgroup[groups[i]] = i >> 5;
}

// ---------------- fused 2-layer GCN + mean pool (one CTA per group) ----------------
__global__ void __launch_bounds__(256) gcn_kernel(const float* __restrict__ x,
                                                  const int* __restrict__ groups,
                                                  const float* __restrict__ W1, const float* __restrict__ b1,
                                                  const float* __restrict__ W2, const float* __restrict__ b2) {
    __shared__ float xsT[256 * 36];
    __shared__ int idx[32];
    const int g = blockIdx.x, c = threadIdx.x;
    if (c < 32) idx[c] = groups[g * 32 + c];
    __syncthreads();
#pragma unroll 4
    for (int ii = 0; ii < 32; ii++)
        xsT[c * 36 + ii] = x[(size_t)idx[ii] * HDIM + c];
    __syncthreads();

    float acc[32];
#pragma unroll
    for (int i = 0; i < 32; i++) acc[i] = 0.f;
#pragma unroll 4
    for (int k = 0; k < 256; k++) {
        float wv = W1[k * HDIM + c];
        const float4* xr = reinterpret_cast<const float4*>(&xsT[k * 36]);
#pragma unroll
        for (int q = 0; q < 8; q++) {
            float4 xv = xr[q];
            acc[q * 4 + 0] = fmaf(xv.x, wv, acc[q * 4 + 0]);
            acc[q * 4 + 1] = fmaf(xv.y, wv, acc[q * 4 + 1]);
            acc[q * 4 + 2] = fmaf(xv.z, wv, acc[q * 4 + 2]);
            acc[q * 4 + 3] = fmaf(xv.w, wv, acc[q * 4 + 3]);
        }
    }
    {
        float s = 0.f;
#pragma unroll
        for (int i = 0; i < 32; i++) s += acc[i];
        float bias = b1[c];
        __syncthreads();
#pragma unroll
        for (int i = 0; i < 32; i++)
            xsT[c * 36 + i] = fmaxf((s + acc[i]) * (1.f / 33.f) + bias, 0.f);
        __syncthreads();
    }
#pragma unroll
    for (int i = 0; i < 32; i++) acc[i] = 0.f;
#pragma unroll 4
    for (int k = 0; k < 256; k++) {
        float wv = W2[k * HDIM + c];
        const float4* xr = reinterpret_cast<const float4*>(&xsT[k * 36]);
#pragma unroll
        for (int q = 0; q < 8; q++) {
            float4 xv = xr[q];
            acc[q * 4 + 0] = fmaf(xv.x, wv, acc[q * 4 + 0]);
            acc[q * 4 + 1] = fmaf(xv.y, wv, acc[q * 4 + 1]);
            acc[q * 4 + 2] = fmaf(xv.z, wv, acc[q * 4 + 2]);
            acc[q * 4 + 3] = fmaf(xv.w, wv, acc[q * 4 + 3]);
        }
    }
    {
        float s = 0.f;
#pragma unroll
        for (int i = 0; i < 32; i++) s += acc[i];
        float bias = b2[c];
        float psum = 0.f;
#pragma unroll
        for (int i = 0; i < 32; i++)
            psum += fmaxf((s + acc[i]) * (1.f / 33.f) + bias, 0.f);
        g_pooled[g * HDIM + c] = psum * (1.f / 32.f);
    }
}

// ---------------- input projection for the 1025 distinct LSTM input rows ----------------
__global__ void __launch_bounds__(1024) zg_kernel(const float* __restrict__ Wih,
                                                  const float* __restrict__ b) {
    __shared__ float v[HDIM];
    int r = blockIdx.x, o = threadIdx.x;
    if (o < HDIM) v[o] = (r < NGROUP) ? g_pooled[r * HDIM + o] : g_goal[o];
    __syncthreads();
    float acc = b[o];
#pragma unroll 8
    for (int k = 0; k < HDIM; k++) acc = fmaf(v[k], Wih[k * 1024 + o], acc);
    g_Z[(size_t)r * 1024 + o] = acc;
}

__device__ __forceinline__ int rowgrp(int t) {
    return (t < NAGENTS) ? g_rowgroup[t] : NGROUP;
}

// ---------------- LSTM: CN-CTA cluster, W_hh register-resident (FFMA2),
// warp-local gate combine, h broadcast via per-peer 64B DSMEM bulk copies ----------------
// Warp w owns units [4w, 4w+4). Lane: gate = lane>>3, sub = lane&7 (32-wide k-chunk).
template <int CN>
__global__ void __launch_bounds__(8 * (256 / CN), 1) lstm_kernel_t(const float* __restrict__ Whh) {
    constexpr int UN  = 256 / CN;    // hidden units per CTA
    constexpr int NT  = 8 * UN;      // threads per CTA
    __shared__ __align__(16) float h_s[2][HDIM];
    __shared__ __align__(16) float h_stage[UN];
    __shared__ __align__(8)  unsigned long long mbar[2];
    const unsigned rank = cluster_rank_();
    const int tid = threadIdx.x;
    const int wid = tid >> 5, lane = tid & 31;
    const int gate = lane >> 3, sub = lane & 7;
    const int obase = gate * 256 + UN * (int)rank + wid * 4;  // 4 consecutive columns
    const int zoff  = obase + (sub & 3);

    // persistent packed weights: 16 k-pairs (k = 32*sub + 2j) x 4 output cols
    unsigned long long wp[64];
#pragma unroll
    for (int j = 0; j < 16; j++) {
        const int k0 = 32 * sub + 2 * j;
#pragma unroll
        for (int c = 0; c < 4; c++)
            wp[j * 4 + c] = pack2(Whh[(size_t)k0 * 1024 + obase + c],
                                  Whh[(size_t)(k0 + 1) * 1024 + obase + c]);
    }

    for (int i = tid; i < HDIM; i += NT) h_s[0][i] = 0.f;

    const unsigned mb_local = smem_u32(&mbar[0]);
    const unsigned stage_a  = smem_u32(&h_stage[0]);
    if (tid == 0) {
        mbar_init(mb_local, 1);
        mbar_init(mb_local + 8, 1);
        mbar_expect_tx(mb_local, HDIM * 4);       // arm buffer 0, phase 0
        mbar_expect_tx(mb_local + 8, HDIM * 4);   // arm buffer 1, phase 0
    }

    // per-peer remote addresses (loop-invariant mapa): threads tid < CN issue bulk copies
    unsigned ra = 0, rm = 0;
    if (tid < CN) {
        unsigned la = smem_u32(&h_s[0][UN * (int)rank]);   // our slice in any peer's buffer
        asm volatile("mapa.shared::cluster.u32 %0, %1, %2;" : "=r"(ra) : "r"(la), "r"(tid));
        asm volatile("mapa.shared::cluster.u32 %0, %1, %2;" : "=r"(rm) : "r"(mb_local), "r"(tid));
    }
    __syncthreads();
    cluster_sync_();   // mbars armed cluster-wide before any incoming tx

    float cst = 0.f;   // meaningful in lanes 0..3 of each warp (unit 4*wid+lane)
    unsigned pha0 = 0, pha1 = 0;

    // depth-3 prefetch pipeline for the input-projection element
    float zgv     = g_Z[(size_t)rowgrp(0) * 1024 + zoff];
    float zg_next = g_Z[(size_t)rowgrp(1) * 1024 + zoff];
    int   rg_next = rowgrp(2);

    for (int t = 0; t < NSTEPS; t++) {
        const int p = t & 1, pn = p ^ 1;
        int   rg_new = rowgrp(t + 3);
        float zg_new = g_Z[(size_t)rg_next * 1024 + zoff];

        if (t) {
            unsigned mb = mb_local + (unsigned)p * 8;
            unsigned ph = p ? pha1 : pha0;
            mbar_wait_cluster(mb, ph);
            if (p) pha1 ^= 1; else pha0 ^= 1;
            if (tid == 0) mbar_expect_tx(mb, HDIM * 4);   // re-arm; ordered before our
        }                                                  // broadcast via the bar below

        // ---- packed dot: 4 outputs over k in [32*sub, 32*sub+32) ----
        unsigned long long a0 = 0, a1 = 0, a2 = 0, a3 = 0;
        const ulonglong2* hp = reinterpret_cast<const ulonglong2*>(&h_s[p][32 * sub]);
#pragma unroll
        for (int j = 0; j < 8; j++) {
            ulonglong2 hv = hp[j];
            ffma2(a0, hv.x, wp[(2 * j) * 4 + 0]);
            ffma2(a1, hv.x, wp[(2 * j) * 4 + 1]);
            ffma2(a2, hv.x, wp[(2 * j) * 4 + 2]);
            ffma2(a3, hv.x, wp[(2 * j) * 4 + 3]);
            ffma2(a0, hv.y, wp[(2 * j + 1) * 4 + 0]);
            ffma2(a1, hv.y, wp[(2 * j + 1) * 4 + 1]);
            ffma2(a2, hv.y, wp[(2 * j + 1) * 4 + 2]);
            ffma2(a3, hv.y, wp[(2 * j + 1) * 4 + 3]);
        }
        float r0 = pairsum(a0), r1 = pairsum(a1), r2 = pairsum(a2), r3 = pairsum(a3);
#pragma unroll
        for (int d = 4; d; d >>= 1) {
            r0 += __shfl_xor_sync(0xffffffffu, r0, d);
            r1 += __shfl_xor_sync(0xffffffffu, r1, d);
            r2 += __shfl_xor_sync(0xffffffffu, r2, d);
            r3 += __shfl_xor_sync(0xffffffffu, r3, d);
        }
        // lanes with sub<4 hold gate value for unit 4*wid+sub
        float v = ((sub == 0) ? r0 : (sub == 1) ? r1 : (sub == 2) ? r2 : r3) + zgv;
        v = (gate == 2) ? tanh_a(v) : sigm_a(v);

        // ---- warp-local combine: gather f,g,o into the i-gate lanes (lane<4) ----
        float vf = __shfl_sync(0xffffffffu, v,  8 + (lane & 7));
        float vg = __shfl_sync(0xffffffffu, v, 16 + (lane & 7));
        float vo = __shfl_sync(0xffffffffu, v, 24 + (lane & 7));
        if (lane < 4) {
            cst = fmaf(vf, cst, v * vg);          // v = sigmoid(i) here
            float hn = vo * tanh_a(cst);
            g_hs[(size_t)t * HDIM + UN * (int)rank + wid * 4 + lane] = hn;
            h_stage[wid * 4 + lane] = hn;
        }
        __syncthreads();                          // all UN staged; also orders re-arm

        // ---- broadcast: one 64B(UN*4) bulk copy per peer, complete_tx at peer ----
        if (t + 1 < NSTEPS && tid < CN) {
            fence_async_shared();                 // staging stores -> async proxy
            bulk_dsmem(ra + (unsigned)(pn * (HDIM * 4)), stage_a, UN * 4,
                       rm + (unsigned)(pn * 8));
        }
        zgv = zg_next; zg_next = zg_new; rg_next = rg_new;
    }
    cluster_sync_();   // symmetric teardown: no in-flight remote traffic at exit
}

// ---------------- output projection + softmax (one warp per row) ----------------
__global__ void __launch_bounds__(256) out_kernel(const float* __restrict__ W,
                                                  const float* __restrict__ b,
                                                  float* __restrict__ out) {
    __shared__ float hrow[8][HDIM];
    int w = threadIdx.x >> 5, l = threadIdx.x & 31;
    int gw = blockIdx.x * 8 + w;
    int nw = gridDim.x * 8;
    float b1v = b[l], b2v = b[32 + l];
    for (int r = gw; r < NSTEPS; r += nw) {
        float4* dst = reinterpret_cast<float4*>(&hrow[w][0]);
        const float4* src = reinterpret_cast<const float4*>(&g_hs[(size_t)r * HDIM]);
        dst[2 * l] = src[2 * l];
        dst[2 * l + 1] = src[2 * l + 1];
        __syncwarp();
        float a1 = b1v, a2 = b2v;
#pragma unroll 4
        for (int k = 0; k < HDIM; k++) {
            float hk = hrow[w][k];
            a1 = fmaf(hk, W[k * 64 + l], a1);
            a2 = fmaf(hk, W[k * 64 + 32 + l], a2);
        }
        float m = fmaxf(a1, a2);
#pragma unroll
        for (int d = 16; d; d >>= 1) m = fmaxf(m, __shfl_xor_sync(0xffffffffu, m, d));
        float e1 = __expf(a1 - m), e2 = __expf(a2 - m);
        float ssum = e1 + e2;
#pragma unroll
        for (int d = 16; d; d >>= 1) ssum += __shfl_xor_sync(0xffffffffu, ssum, d);
        float inv = __fdividef(1.f, ssum);
        out[(size_t)r * 64 + l]      = e1 * inv;
        out[(size_t)r * 64 + 32 + l] = e2 * inv;
        __syncwarp();
    }
}

// ---------------- launch ----------------
extern "C" void kernel_launch(void* const* d_in, const int* in_sizes, int n_in,
                              void* d_out, int out_size) {
    const float* agent_state  = (const float*)d_in[0];
    const float* goal_state   = (const float*)d_in[1];
    const int*   agent_groups = (const int*)  d_in[2];
    const float* W_goal = (const float*)d_in[3];
    const float* b_goal = (const float*)d_in[4];
    const float* W_g1   = (const float*)d_in[5];
    const float* b_g1   = (const float*)d_in[6];
    const float* W_g2   = (const float*)d_in[7];
    const float* b_g2   = (const float*)d_in[8];
    const float* W_ih   = (const float*)d_in[9];
    const float* W_hh   = (const float*)d_in[10];
    const float* b_lstm = (const float*)d_in[11];
    const float* W_act  = (const float*)d_in[12];
    const float* b_act  = (const float*)d_in[13];
    float* out = (float*)d_out;

    goal_kernel<<<1, 256>>>(goal_state, W_goal, b_goal);
    rowgroup_kernel<<<NAGENTS / 256, 256>>>(agent_groups);
    gcn_kernel<<<NGROUP, 256>>>(agent_state, agent_groups, W_g1, b_g1, W_g2, b_g2);
    zg_kernel<<<NGROUP + 1, 1024>>>(W_ih, b_lstm);

    // LSTM: prefer a 16-CTA cluster (needs non-portable attr); fall back to 8.
    cudaError_t e = cudaFuncSetAttribute(
        (const void*)lstm_kernel_t<16>,
        cudaFuncAttributeNonPortableClusterSizeAllowed, 1);
    bool launched16 = false;
    if (e == cudaSuccess) {
        cudaLaunchConfig_t cfg = {};
        cfg.gridDim  = dim3(16, 1, 1);
        cfg.blockDim = dim3(128, 1, 1);
        cfg.stream   = 0;
        cudaLaunchAttribute at[1];
        at[0].id = cudaLaunchAttributeClusterDimension;
        at[0].val.clusterDim.x = 16; at[0].val.clusterDim.y = 1; at[0].val.clusterDim.z = 1;
        cfg.attrs = at; cfg.numAttrs = 1;
        launched16 = (cudaLaunchKernelEx(&cfg, lstm_kernel_t<16>, W_hh) == cudaSuccess);
    }
    if (!launched16) {
        (void)cudaGetLastError();
        cudaLaunchConfig_t cfg = {};
        cfg.gridDim  = dim3(8, 1, 1);
        cfg.blockDim = dim3(256, 1, 1);
        cfg.stream   = 0;
        cudaLaunchAttribute at[1];
        at[0].id = cudaLaunchAttributeClusterDimension;
        at[0].val.clusterDim.x = 8; at[0].val.clusterDim.y = 1; at[0].val.clusterDim.z = 1;
        cfg.attrs = at; cfg.numAttrs = 1;
        cudaLaunchKernelEx(&cfg, lstm_kernel_t<8>, W_hh);
    }

    out_kernel<<<512, 256>>>(W_act, b_act, out);
}

// round 9
// speedup vs baseline: 1.2419x; 1.2419x over previous
#include <cuda_runtime.h>
#include <cstdint>
#include <cstddef>

#define NAGENTS 32768
#define HDIM    256
#define NGROUP  1024
#define NSTEPS  (NAGENTS + 1)

// ---------------- scratch (__device__ globals; no allocation) ----------------
__device__ float g_goal[HDIM];
__device__ float g_pooled[NGROUP * HDIM];
__device__ float g_Z[(NGROUP + 1) * 4 * HDIM];
__device__ int   g_rowgroup[NAGENTS];
__device__ float g_hs[(size_t)NSTEPS * HDIM];

// ---------------- helpers ----------------
__device__ __forceinline__ unsigned smem_u32(const void* p) {
    return (unsigned)__cvta_generic_to_shared(p);
}
__device__ __forceinline__ unsigned cluster_rank_() {
    unsigned r; asm("mov.u32 %0, %%cluster_ctarank;" : "=r"(r)); return r;
}
__device__ __forceinline__ void cluster_sync_() {
    asm volatile("barrier.cluster.arrive.aligned;\n\tbarrier.cluster.wait.aligned;" ::: "memory");
}
// fast nonlinearities: single-MUFU tanh
__device__ __forceinline__ float tanh_a(float x) {
    float y; asm("tanh.approx.f32 %0, %1;" : "=f"(y) : "f"(x)); return y;
}
__device__ __forceinline__ float sigm_a(float x) {
    return fmaf(0.5f, tanh_a(0.5f * x), 0.5f);
}
// packed fp32x2 FFMA2 (PTX-only)
__device__ __forceinline__ void ffma2(unsigned long long& d, unsigned long long a, unsigned long long b) {
    asm("fma.rn.f32x2 %0, %1, %2, %0;" : "+l"(d) : "l"(a), "l"(b));
}
__device__ __forceinline__ unsigned long long pack2(float lo, float hi) {
    unsigned long long r; asm("mov.b64 %0, {%1, %2};" : "=l"(r) : "f"(lo), "f"(hi)); return r;
}
__device__ __forceinline__ float pairsum(unsigned long long v) {
    float lo, hi; asm("mov.b64 {%0, %1}, %2;" : "=f"(lo), "=f"(hi) : "l"(v));
    return lo + hi;
}
// mbarrier ops
__device__ __forceinline__ void mbar_init(unsigned a, unsigned cnt) {
    asm volatile("mbarrier.init.shared.b64 [%0], %1;" :: "r"(a), "r"(cnt) : "memory");
}
__device__ __forceinline__ void mbar_expect_tx(unsigned a, unsigned bytes) {
    asm volatile("mbarrier.arrive.expect_tx.shared.b64 _, [%0], %1;" :: "r"(a), "r"(bytes) : "memory");
}
__device__ __forceinline__ void mbar_wait_cluster(unsigned a, unsigned parity) {
    asm volatile(
        "{\n\t"
        ".reg .pred P;\n\t"
        "WAIT_%=:\n\t"
        "mbarrier.try_wait.parity.acquire.cluster.shared::cta.b64 P, [%0], %1, 0x989680;\n\t"
        "@P bra.uni DONE_%=;\n\t"
        "bra.uni WAIT_%=;\n\t"
        "DONE_%=:\n\t"
        "}"
        :: "r"(a), "r"(parity) : "memory");
}
// 16-byte async remote store with tx accounting on the peer's mbarrier
__device__ __forceinline__ void st_async_v4(unsigned daddr, float x, float y, float z, float w,
                                            unsigned mbaddr) {
    asm volatile("st.async.shared::cluster.mbarrier::complete_tx::bytes.v4.b32 "
                 "[%0], {%1, %2, %3, %4}, [%5];"
                 :: "r"(daddr), "r"(__float_as_uint(x)), "r"(__float_as_uint(y)),
                    "r"(__float_as_uint(z)), "r"(__float_as_uint(w)), "r"(mbaddr) : "memory");
}

// ---------------- goal embedding ----------------
__global__ void __launch_bounds__(256) goal_kernel(const float* __restrict__ gs_in,
                                                   const float* __restrict__ Wg,
                                                   const float* __restrict__ bg) {
    __shared__ float gs[HDIM];
    int c = threadIdx.x;
    gs[c] = gs_in[c];
    __syncthreads();
    float acc = bg[c];
#pragma unroll 8
    for (int k = 0; k < HDIM; k++) acc = fmaf(gs[k], Wg[k * HDIM + c], acc);
    g_goal[c] = fmaxf(acc, 0.f);
}

// ---------------- inverse scatter map ----------------
__global__ void rowgroup_kernel(const int* __restrict__ groups) {
    int i = blockIdx.x * blockDim.x + threadIdx.x;
    g_rowgroup[groups[i]] = i >> 5;
}

// ---------------- fused 2-layer GCN + mean pool (one CTA per group) ----------------
__global__ void __launch_bounds__(256) gcn_kernel(const float* __restrict__ x,
                                                  const int* __restrict__ groups,
                                                  const float* __restrict__ W1, const float* __restrict__ b1,
                                                  const float* __restrict__ W2, const float* __restrict__ b2) {
    __shared__ float xsT[256 * 36];
    __shared__ int idx[32];
    const int g = blockIdx.x, c = threadIdx.x;
    if (c < 32) idx[c] = groups[g * 32 + c];
    __syncthreads();
#pragma unroll 4
    for (int ii = 0; ii < 32; ii++)
        xsT[c * 36 + ii] = x[(size_t)idx[ii] * HDIM + c];
    __syncthreads();

    float acc[32];
#pragma unroll
    for (int i = 0; i < 32; i++) acc[i] = 0.f;
#pragma unroll 4
    for (int k = 0; k < 256; k++) {
        float wv = W1[k * HDIM + c];
        const float4* xr = reinterpret_cast<const float4*>(&xsT[k * 36]);
#pragma unroll
        for (int q = 0; q < 8; q++) {
            float4 xv = xr[q];
            acc[q * 4 + 0] = fmaf(xv.x, wv, acc[q * 4 + 0]);
            acc[q * 4 + 1] = fmaf(xv.y, wv, acc[q * 4 + 1]);
            acc[q * 4 + 2] = fmaf(xv.z, wv, acc[q * 4 + 2]);
            acc[q * 4 + 3] = fmaf(xv.w, wv, acc[q * 4 + 3]);
        }
    }
    {
        float s = 0.f;
#pragma unroll
        for (int i = 0; i < 32; i++) s += acc[i];
        float bias = b1[c];
        __syncthreads();
#pragma unroll
        for (int i = 0; i < 32; i++)
            xsT[c * 36 + i] = fmaxf((s + acc[i]) * (1.f / 33.f) + bias, 0.f);
        __syncthreads();
    }
#pragma unroll
    for (int i = 0; i < 32; i++) acc[i] = 0.f;
#pragma unroll 4
    for (int k = 0; k < 256; k++) {
        float wv = W2[k * HDIM + c];
        const float4* xr = reinterpret_cast<const float4*>(&xsT[k * 36]);
#pragma unroll
        for (int q = 0; q < 8; q++) {
            float4 xv = xr[q];
            acc[q * 4 + 0] = fmaf(xv.x, wv, acc[q * 4 + 0]);
            acc[q * 4 + 1] = fmaf(xv.y, wv, acc[q * 4 + 1]);
            acc[q * 4 + 2] = fmaf(xv.z, wv, acc[q * 4 + 2]);
            acc[q * 4 + 3] = fmaf(xv.w, wv, acc[q * 4 + 3]);
        }
    }
    {
        float s = 0.f;
#pragma unroll
        for (int i = 0; i < 32; i++) s += acc[i];
        float bias = b2[c];
        float psum = 0.f;
#pragma unroll
        for (int i = 0; i < 32; i++)
            psum += fmaxf((s + acc[i]) * (1.f / 33.f) + bias, 0.f);
        g_pooled[g * HDIM + c] = psum * (1.f / 32.f);
    }
}

// ---------------- input projection for the 1025 distinct LSTM input rows ----------------
__global__ void __launch_bounds__(1024) zg_kernel(const float* __restrict__ Wih,
                                                  const float* __restrict__ b) {
    __shared__ float v[HDIM];
    int r = blockIdx.x, o = threadIdx.x;
    if (o < HDIM) v[o] = (r < NGROUP) ? g_pooled[r * HDIM + o] : g_goal[o];
    __syncthreads();
    float acc = b[o];
#pragma unroll 8
    for (int k = 0; k < HDIM; k++) acc = fmaf(v[k], Wih[k * 1024 + o], acc);
    g_Z[(size_t)r * 1024 + o] = acc;
}

__device__ __forceinline__ int rowgrp(int t) {
    return (t < NAGENTS) ? g_rowgroup[t] : NGROUP;
}

// ---------------- LSTM: CN-CTA cluster, W_hh register-resident (FFMA2),
// warp-local gate combine, broadcast = one st.async.v4 per peer per warp leader.
// Warp w owns units [4w, 4w+4). Lane: gate = lane>>3, sub = lane&7.
template <int CN>
__global__ void __launch_bounds__(8 * (256 / CN), 1) lstm_kernel_t(const float* __restrict__ Whh) {
    constexpr int UN  = 256 / CN;    // hidden units per CTA
    constexpr int NT  = 8 * UN;      // threads per CTA
    __shared__ __align__(16) float h_s[2][HDIM];
    __shared__ __align__(8)  unsigned long long mbar[2];
    const unsigned rank = cluster_rank_();
    const int tid = threadIdx.x;
    const int wid = tid >> 5, lane = tid & 31;
    const int gate = lane >> 3, sub = lane & 7;
    const int obase = gate * 256 + UN * (int)rank + wid * 4;  // 4 consecutive columns
    const int zoff  = obase + (sub & 3);

    // persistent packed weights: 16 k-pairs (k = 32*sub + 2j) x 4 output cols
    unsigned long long wp[64];
#pragma unroll
    for (int j = 0; j < 16; j++) {
        const int k0 = 32 * sub + 2 * j;
#pragma unroll
        for (int c = 0; c < 4; c++)
            wp[j * 4 + c] = pack2(Whh[(size_t)k0 * 1024 + obase + c],
                                  Whh[(size_t)(k0 + 1) * 1024 + obase + c]);
    }

    for (int i = tid; i < HDIM; i += NT) h_s[0][i] = 0.f;

    const unsigned mb_local = smem_u32(&mbar[0]);
    if (tid == 0) {
        mbar_init(mb_local, 1);
        mbar_init(mb_local + 8, 1);
        mbar_expect_tx(mb_local, HDIM * 4);       // arm buffer 0, phase 0
        mbar_expect_tx(mb_local + 8, HDIM * 4);   // arm buffer 1, phase 0
    }

    // Per-peer remote address of THIS WARP's 16B slice inside h_s[0] (rank-rotated
    // send order so consumers see uniform arrival, not a burst aimed at CTA 0).
    // Remote mbar = slice addr + constant delta (mapa preserves intra-CTA offsets).
    const unsigned sl_local = smem_u32(&h_s[0][UN * (int)rank + wid * 4]);
    const int mb_delta = (int)mb_local - (int)sl_local;
    unsigned ra16[CN];
#pragma unroll
    for (int i = 0; i < CN; i++) {
        unsigned peer = (rank + (unsigned)i) & (CN - 1);
        asm volatile("mapa.shared::cluster.u32 %0, %1, %2;" : "=r"(ra16[i]) : "r"(sl_local), "r"(peer));
    }
    __syncthreads();
    cluster_sync_();   // mbars armed cluster-wide before any incoming tx

    float cst = 0.f;   // meaningful in lanes 0..3 (unit 4*wid+lane)
    unsigned pha0 = 0, pha1 = 0;

    // depth-3 prefetch pipeline for the input-projection element
    float zgv     = g_Z[(size_t)rowgrp(0) * 1024 + zoff];
    float zg_next = g_Z[(size_t)rowgrp(1) * 1024 + zoff];
    int   rg_next = rowgrp(2);

    for (int t = 0; t < NSTEPS; t++) {
        const int p = t & 1, pn = p ^ 1;
        int   rg_new = rowgrp(t + 3);
        float zg_new = g_Z[(size_t)rg_next * 1024 + zoff];

        if (t) {
            unsigned mb = mb_local + (unsigned)p * 8;
            unsigned ph = p ? pha1 : pha0;
            mbar_wait_cluster(mb, ph);
            if (p) pha1 ^= 1; else pha0 ^= 1;
            if (tid == 0) mbar_expect_tx(mb, HDIM * 4);   // re-arm; ordered before peers'
        }                                                  // next tx via the send round-trip

        // ---- packed dot: 4 outputs over k in [32*sub, 32*sub+32) ----
        unsigned long long a0 = 0, a1 = 0, a2 = 0, a3 = 0;
        const ulonglong2* hp = reinterpret_cast<const ulonglong2*>(&h_s[p][32 * sub]);
#pragma unroll
        for (int j = 0; j < 8; j++) {
            ulonglong2 hv = hp[j];
            ffma2(a0, hv.x, wp[(2 * j) * 4 + 0]);
            ffma2(a1, hv.x, wp[(2 * j) * 4 + 1]);
            ffma2(a2, hv.x, wp[(2 * j) * 4 + 2]);
            ffma2(a3, hv.x, wp[(2 * j) * 4 + 3]);
            ffma2(a0, hv.y, wp[(2 * j + 1) * 4 + 0]);
            ffma2(a1, hv.y, wp[(2 * j + 1) * 4 + 1]);
            ffma2(a2, hv.y, wp[(2 * j + 1) * 4 + 2]);
            ffma2(a3, hv.y, wp[(2 * j + 1) * 4 + 3]);
        }
        float r0 = pairsum(a0), r1 = pairsum(a1), r2 = pairsum(a2), r3 = pairsum(a3);
#pragma unroll
        for (int d = 4; d; d >>= 1) {
            r0 += __shfl_xor_sync(0xffffffffu, r0, d);
            r1 += __shfl_xor_sync(0xffffffffu, r1, d);
            r2 += __shfl_xor_sync(0xffffffffu, r2, d);
            r3 += __shfl_xor_sync(0xffffffffu, r3, d);
        }
        // lanes with sub<4 hold the gate value for unit 4*wid+sub
        float v = ((sub == 0) ? r0 : (sub == 1) ? r1 : (sub == 2) ? r2 : r3) + zgv;
        v = (gate == 2) ? tanh_a(v) : sigm_a(v);

        // ---- warp-local combine: f,g,o gathered into i-gate lanes ----
        float vf = __shfl_sync(0xffffffffu, v,  8 + (lane & 7));
        float vg = __shfl_sync(0xffffffffu, v, 16 + (lane & 7));
        float vo = __shfl_sync(0xffffffffu, v, 24 + (lane & 7));
        cst = fmaf(vf, cst, v * vg);              // v = sigmoid(i) in lanes 0..3
        float hn = vo * tanh_a(cst);
        if (lane < 4)
            g_hs[(size_t)t * HDIM + UN * (int)rank + wid * 4 + lane] = hn;

        // gather the warp's 4 unit-values into every lane (only lane 0 sends)
        float h0 = __shfl_sync(0xffffffffu, hn, 0);
        float h1 = __shfl_sync(0xffffffffu, hn, 1);
        float h2 = __shfl_sync(0xffffffffu, hn, 2);
        float h3 = __shfl_sync(0xffffffffu, hn, 3);

        // ---- broadcast: one 16B st.async per peer, rank-rotated order ----
        if (t + 1 < NSTEPS && lane == 0) {
            const unsigned dofs = (unsigned)(pn * (HDIM * 4));
            const unsigned mofs = (unsigned)(pn * 8) + (unsigned)mb_delta;
#pragma unroll
            for (int i = 0; i < CN; i++)
                st_async_v4(ra16[i] + dofs, h0, h1, h2, h3, ra16[i] + mofs);
        }
        zgv = zg_next; zg_next = zg_new; rg_next = rg_new;
    }
    cluster_sync_();   // symmetric teardown: no in-flight remote traffic at exit
}

// ---------------- output projection + softmax (one warp per row) ----------------
__global__ void __launch_bounds__(256) out_kernel(const float* __restrict__ W,
                                                  const float* __restrict__ b,
                                                  float* __restrict__ out) {
    __shared__ float hrow[8][HDIM];
    int w = threadIdx.x >> 5, l = threadIdx.x & 31;
    int gw = blockIdx.x * 8 + w;
    int nw = gridDim.x * 8;
    float b1v = b[l], b2v = b[32 + l];
    for (int r = gw; r < NSTEPS; r += nw) {
        float4* dst = reinterpret_cast<float4*>(&hrow[w][0]);
        const float4* src = reinterpret_cast<const float4*>(&g_hs[(size_t)r * HDIM]);
        dst[2 * l] = src[2 * l];
        dst[2 * l + 1] = src[2 * l + 1];
        __syncwarp();
        float a1 = b1v, a2 = b2v;
#pragma unroll 4
        for (int k = 0; k < HDIM; k++) {
            float hk = hrow[w][k];
            a1 = fmaf(hk, W[k * 64 + l], a1);
            a2 = fmaf(hk, W[k * 64 + 32 + l], a2);
        }
        float m = fmaxf(a1, a2);
#pragma unroll
        for (int d = 16; d; d >>= 1) m = fmaxf(m, __shfl_xor_sync(0xffffffffu, m, d));
        float e1 = __expf(a1 - m), e2 = __expf(a2 - m);
        float ssum = e1 + e2;
#pragma unroll
        for (int d = 16; d; d >>= 1) ssum += __shfl_xor_sync(0xffffffffu, ssum, d);
        float inv = __fdividef(1.f, ssum);
        out[(size_t)r * 64 + l]      = e1 * inv;
        out[(size_t)r * 64 + 32 + l] = e2 * inv;
        __syncwarp();
    }
}

// ---------------- launch ----------------
extern "C" void kernel_launch(void* const* d_in, const int* in_sizes, int n_in,
                              void* d_out, int out_size) {
    const float* agent_state  = (const float*)d_in[0];
    const float* goal_state   = (const float*)d_in[1];
    const int*   agent_groups = (const int*)  d_in[2];
    const float* W_goal = (const float*)d_in[3];
    const float* b_goal = (const float*)d_in[4];
    const float* W_g1   = (const float*)d_in[5];
    const float* b_g1   = (const float*)d_in[6];
    const float* W_g2   = (const float*)d_in[7];
    const float* b_g2   = (const float*)d_in[8];
    const float* W_ih   = (const float*)d_in[9];
    const float* W_hh   = (const float*)d_in[10];
    const float* b_lstm = (const float*)d_in[11];
    const float* W_act  = (const float*)d_in[12];
    const float* b_act  = (const float*)d_in[13];
    float* out = (float*)d_out;

    goal_kernel<<<1, 256>>>(goal_state, W_goal, b_goal);
    rowgroup_kernel<<<NAGENTS / 256, 256>>>(agent_groups);
    gcn_kernel<<<NGROUP, 256>>>(agent_state, agent_groups, W_g1, b_g1, W_g2, b_g2);
    zg_kernel<<<NGROUP + 1, 1024>>>(W_ih, b_lstm);

    // LSTM: prefer a 16-CTA cluster (needs non-portable attr); fall back to 8.
    cudaError_t e = cudaFuncSetAttribute(
        (const void*)lstm_kernel_t<16>,
        cudaFuncAttributeNonPortableClusterSizeAllowed, 1);
    bool launched16 = false;
    if (e == cudaSuccess) {
        cudaLaunchConfig_t cfg = {};
        cfg.gridDim  = dim3(16, 1, 1);
        cfg.blockDim = dim3(128, 1, 1);
        cfg.stream   = 0;
        cudaLaunchAttribute at[1];
        at[0].id = cudaLaunchAttributeClusterDimension;
        at[0].val.clusterDim.x = 16; at[0].val.clusterDim.y = 1; at[0].val.clusterDim.z = 1;
        cfg.attrs = at; cfg.numAttrs = 1;
        launched16 = (cudaLaunchKernelEx(&cfg, lstm_kernel_t<16>, W_hh) == cudaSuccess);
    }
    if (!launched16) {
        (void)cudaGetLastError();
        cudaLaunchConfig_t cfg = {};
        cfg.gridDim  = dim3(8, 1, 1);
        cfg.blockDim = dim3(256, 1, 1);
        cfg.stream   = 0;
        cudaLaunchAttribute at[1];
        at[0].id = cudaLaunchAttributeClusterDimension;
        at[0].val.clusterDim.x = 8; at[0].val.clusterDim.y = 1; at[0].val.clusterDim.z = 1;
        cfg.attrs = at; cfg.numAttrs = 1;
        cudaLaunchKernelEx(&cfg, lstm_kernel_t<8>, W_hh);
    }

    out_kernel<<<512, 256>>>(W_act, b_act, out);
}